// round 1
// baseline (speedup 1.0000x reference)
#include <cuda_runtime.h>

#define SQ 2048
#define SK 2048
#define NB 8
#define DIM 1024
#define INNER 128
#define NH 4
#define HD 32

// Scratch (allocation-free): qkv projections + attention output
__device__ float g_qkv[3u * NB * INNER * SK];   // [sel][n][e][s]   25.2 MB
__device__ float g_x[(size_t)NB * SQ * INNER];  // [n][p][e]         8.4 MB

// ---------------------------------------------------------------------------
// Projection: C[e,s] = sum_d W[e,d] * X[s,n,d]   (per n, per sel in {q,k,v})
// Tile: 128 (all e) x 64 s, BK = 32.
// ---------------------------------------------------------------------------
__global__ void proj_kernel(const float* __restrict__ query,
                            const float* __restrict__ key_feat,
                            const float* __restrict__ Wq,
                            const float* __restrict__ Wk,
                            const float* __restrict__ Wv) {
    const int s0  = blockIdx.x * 64;
    const int n   = blockIdx.y;
    const int sel = blockIdx.z;
    const float* __restrict__ X = (sel == 0) ? query : key_feat;
    const float* __restrict__ W = (sel == 0) ? Wq : (sel == 1 ? Wk : Wv);

    __shared__ float Ws[32][129];  // [d_off][e]
    __shared__ float Xs[32][65];   // [d_off][s_off]

    const int tid = threadIdx.x;
    const int te  = tid & 15;   // 16 groups -> 8 e each
    const int ts  = tid >> 4;   // 16 groups -> 4 s each

    float acc[8][4];
#pragma unroll
    for (int i = 0; i < 8; i++)
#pragma unroll
        for (int j = 0; j < 4; j++) acc[i][j] = 0.f;

    for (int d0 = 0; d0 < DIM; d0 += 32) {
        // W tile: 128 e x 32 d (coalesced over d)
#pragma unroll
        for (int it = 0; it < 16; it++) {
            int i = tid + it * 256;
            int dd = i & 31, e = i >> 5;
            Ws[dd][e] = W[(size_t)e * DIM + d0 + dd];
        }
        // X tile: 32 d x 64 s (coalesced over d)
#pragma unroll
        for (int it = 0; it < 8; it++) {
            int i = tid + it * 256;
            int dd = i & 31, ss = i >> 5;
            Xs[dd][ss] = X[(size_t)(s0 + ss) * (NB * DIM) + (size_t)n * DIM + d0 + dd];
        }
        __syncthreads();
#pragma unroll
        for (int kk = 0; kk < 32; kk++) {
            float a[8], b[4];
#pragma unroll
            for (int i = 0; i < 8; i++) a[i] = Ws[kk][te * 8 + i];
#pragma unroll
            for (int j = 0; j < 4; j++) b[j] = Xs[kk][ts * 4 + j];
#pragma unroll
            for (int i = 0; i < 8; i++)
#pragma unroll
                for (int j = 0; j < 4; j++) acc[i][j] += a[i] * b[j];
        }
        __syncthreads();
    }

    float* __restrict__ out = g_qkv + ((size_t)sel * NB + n) * INNER * SK;
#pragma unroll
    for (int i = 0; i < 8; i++) {
        int e = te * 8 + i;
#pragma unroll
        for (int j = 0; j < 4; j++) {
            out[(size_t)e * SK + s0 + ts * 4 + j] = acc[i][j];
        }
    }
}

// ---------------------------------------------------------------------------
// Flash attention: 1 thread = 1 query row. Online softmax over 32-wide K/V
// chunks staged in shared memory (broadcast reads during compute).
// ---------------------------------------------------------------------------
__global__ void attn_kernel() {
    const int p0 = blockIdx.x * 128;
    const int p  = p0 + threadIdx.x;
    const int h  = blockIdx.y;
    const int n  = blockIdx.z;

    const float* __restrict__ q = g_qkv + ((size_t)0 * NB + n) * INNER * SK + (size_t)(h * HD) * SK;
    const float* __restrict__ k = g_qkv + ((size_t)1 * NB + n) * INNER * SK + (size_t)(h * HD) * SK;
    const float* __restrict__ v = g_qkv + ((size_t)2 * NB + n) * INNER * SK + (size_t)(h * HD) * SK;

    float qr[HD];
#pragma unroll
    for (int c = 0; c < HD; c++) qr[c] = q[(size_t)c * SQ + p];

    float m = -1e30f, l = 0.f;
    float acc[HD];
#pragma unroll
    for (int c = 0; c < HD; c++) acc[c] = 0.f;

    __shared__ float ks[HD][33];
    __shared__ float vs[HD][33];

    const float scale = 0.17677669529663687f;  // 1/sqrt(32)

    for (int k0 = 0; k0 < SK; k0 += 32) {
#pragma unroll
        for (int it = 0; it < 8; it++) {
            int i = threadIdx.x + it * 128;
            int c = i >> 5, kk = i & 31;
            ks[c][kk] = k[(size_t)c * SK + k0 + kk];
            vs[c][kk] = v[(size_t)c * SK + k0 + kk];
        }
        __syncthreads();

        float s[32];
        float mloc = m;
#pragma unroll
        for (int kk = 0; kk < 32; kk++) {
            float t = 0.f;
#pragma unroll
            for (int c = 0; c < HD; c++) t += qr[c] * ks[c][kk];
            t *= scale;
            s[kk] = t;
            mloc = fmaxf(mloc, t);
        }
        float corr = __expf(m - mloc);
        m = mloc;
        l *= corr;
#pragma unroll
        for (int c = 0; c < HD; c++) acc[c] *= corr;
#pragma unroll
        for (int kk = 0; kk < 32; kk++) {
            float pk = __expf(s[kk] - m);
            l += pk;
#pragma unroll
            for (int c = 0; c < HD; c++) acc[c] += pk * vs[c][kk];
        }
        __syncthreads();
    }

    const float inv = 1.f / l;

    // Stage through smem for (partially) coalesced store
    __shared__ float xs[128][HD + 1];
#pragma unroll
    for (int c = 0; c < HD; c++) xs[threadIdx.x][c] = acc[c] * inv;
    __syncthreads();

    float* __restrict__ xout = g_x + (size_t)n * SQ * INNER + h * HD;
#pragma unroll
    for (int it = 0; it < 32; it++) {
        int i = threadIdx.x + it * 128;
        int row = i >> 5, cc = i & 31;
        xout[(size_t)(p0 + row) * INNER + cc] = xs[row][cc];
    }
}

// ---------------------------------------------------------------------------
// Up-projection: out[p,n,d] = sum_e x[n,p,e] * Wup[d,e]
// Rows r = n*SQ + p (M = 16384), cols d (1024), K = 128.
// ---------------------------------------------------------------------------
__global__ void up_kernel(const float* __restrict__ Wup, float* __restrict__ out) {
    const int d0 = blockIdx.x * 64;
    const int r0 = blockIdx.y * 64;

    __shared__ float Xs[32][65];  // [e_off][r_off]
    __shared__ float Ws[32][65];  // [e_off][d_off]

    const int tid = threadIdx.x;
    const int tr = tid & 15;   // 4 rows each
    const int td = tid >> 4;   // 4 cols each

    float acc[4][4];
#pragma unroll
    for (int i = 0; i < 4; i++)
#pragma unroll
        for (int j = 0; j < 4; j++) acc[i][j] = 0.f;

    for (int e0 = 0; e0 < INNER; e0 += 32) {
#pragma unroll
        for (int it = 0; it < 8; it++) {
            int i = tid + it * 256;
            int ee = i & 31, rr = i >> 5;
            Xs[ee][rr] = g_x[(size_t)(r0 + rr) * INNER + e0 + ee];
            Ws[ee][rr] = Wup[(size_t)(d0 + rr) * INNER + e0 + ee];
        }
        __syncthreads();
#pragma unroll
        for (int kk = 0; kk < 32; kk++) {
            float a[4], b[4];
#pragma unroll
            for (int i = 0; i < 4; i++) a[i] = Xs[kk][tr * 4 + i];
#pragma unroll
            for (int j = 0; j < 4; j++) b[j] = Ws[kk][td * 4 + j];
#pragma unroll
            for (int i = 0; i < 4; i++)
#pragma unroll
                for (int j = 0; j < 4; j++) acc[i][j] += a[i] * b[j];
        }
        __syncthreads();
    }

#pragma unroll
    for (int i = 0; i < 4; i++) {
        int r = r0 + tr * 4 + i;
        int n = r >> 11;        // r / SQ
        int pp = r & 2047;      // r % SQ
#pragma unroll
        for (int j = 0; j < 4; j++) {
            out[((size_t)pp * NB + n) * DIM + d0 + td * 4 + j] = acc[i][j];
        }
    }
}

// ---------------------------------------------------------------------------
extern "C" void kernel_launch(void* const* d_in, const int* in_sizes, int n_in,
                              void* d_out, int out_size) {
    const float* query    = (const float*)d_in[0];
    const float* key_feat = (const float*)d_in[1];
    const float* Wq       = (const float*)d_in[2];
    const float* Wk       = (const float*)d_in[3];
    const float* Wv       = (const float*)d_in[4];
    const float* Wup      = (const float*)d_in[5];
    float* out            = (float*)d_out;

    dim3 g1(SK / 64, NB, 3);
    proj_kernel<<<g1, 256>>>(query, key_feat, Wq, Wk, Wv);

    dim3 g2(SQ / 128, NH, NB);
    attn_kernel<<<g2, 128>>>();

    dim3 g3(DIM / 64, (NB * SQ) / 64);
    up_kernel<<<g3, 256>>>(Wup, out);
}

// round 2
// speedup vs baseline: 1.0006x; 1.0006x over previous
#include <cuda_runtime.h>

#define SQ 2048
#define SK 2048
#define NB 8
#define DIM 1024
#define INNER 128
#define NH 4
#define HD 32

// Scratch (allocation-free): qkv projections + attention output
__device__ float g_qkv[3u * NB * INNER * SK];   // [sel][n][e][s]   25.2 MB
__device__ float g_x[(size_t)NB * SQ * INNER];  // [n][p][e]         8.4 MB

// ---------------------------------------------------------------------------
// Projection: C[e,s] = sum_d W[e,d] * X[s,n,d]   (per n, per sel in {q,k,v})
// Tile: 128 (all e) x 64 s, BK = 32.
// ---------------------------------------------------------------------------
__global__ void proj_kernel(const float* __restrict__ query,
                            const float* __restrict__ key_feat,
                            const float* __restrict__ Wq,
                            const float* __restrict__ Wk,
                            const float* __restrict__ Wv) {
    const int s0  = blockIdx.x * 64;
    const int n   = blockIdx.y;
    const int sel = blockIdx.z;
    const float* __restrict__ X = (sel == 0) ? query : key_feat;
    const float* __restrict__ W = (sel == 0) ? Wq : (sel == 1 ? Wk : Wv);

    __shared__ float Ws[32][129];  // [d_off][e]
    __shared__ float Xs[32][65];   // [d_off][s_off]

    const int tid = threadIdx.x;
    const int te  = tid & 15;   // 16 groups -> 8 e each
    const int ts  = tid >> 4;   // 16 groups -> 4 s each

    float acc[8][4];
#pragma unroll
    for (int i = 0; i < 8; i++)
#pragma unroll
        for (int j = 0; j < 4; j++) acc[i][j] = 0.f;

    for (int d0 = 0; d0 < DIM; d0 += 32) {
        // W tile: 128 e x 32 d (coalesced over d)
#pragma unroll
        for (int it = 0; it < 16; it++) {
            int i = tid + it * 256;
            int dd = i & 31, e = i >> 5;
            Ws[dd][e] = W[(size_t)e * DIM + d0 + dd];
        }
        // X tile: 32 d x 64 s (coalesced over d)
#pragma unroll
        for (int it = 0; it < 8; it++) {
            int i = tid + it * 256;
            int dd = i & 31, ss = i >> 5;
            Xs[dd][ss] = X[(size_t)(s0 + ss) * (NB * DIM) + (size_t)n * DIM + d0 + dd];
        }
        __syncthreads();
#pragma unroll
        for (int kk = 0; kk < 32; kk++) {
            float a[8], b[4];
#pragma unroll
            for (int i = 0; i < 8; i++) a[i] = Ws[kk][te * 8 + i];
#pragma unroll
            for (int j = 0; j < 4; j++) b[j] = Xs[kk][ts * 4 + j];
#pragma unroll
            for (int i = 0; i < 8; i++)
#pragma unroll
                for (int j = 0; j < 4; j++) acc[i][j] += a[i] * b[j];
        }
        __syncthreads();
    }

    float* __restrict__ out = g_qkv + ((size_t)sel * NB + n) * INNER * SK;
#pragma unroll
    for (int i = 0; i < 8; i++) {
        int e = te * 8 + i;
#pragma unroll
        for (int j = 0; j < 4; j++) {
            out[(size_t)e * SK + s0 + ts * 4 + j] = acc[i][j];
        }
    }
}

// ---------------------------------------------------------------------------
// Flash attention: 1 thread = 1 query row. Online softmax over 32-wide K/V
// chunks staged in shared memory (broadcast reads during compute).
// ---------------------------------------------------------------------------
__global__ void attn_kernel() {
    const int p0 = blockIdx.x * 128;
    const int p  = p0 + threadIdx.x;
    const int h  = blockIdx.y;
    const int n  = blockIdx.z;

    const float* __restrict__ q = g_qkv + ((size_t)0 * NB + n) * INNER * SK + (size_t)(h * HD) * SK;
    const float* __restrict__ k = g_qkv + ((size_t)1 * NB + n) * INNER * SK + (size_t)(h * HD) * SK;
    const float* __restrict__ v = g_qkv + ((size_t)2 * NB + n) * INNER * SK + (size_t)(h * HD) * SK;

    float qr[HD];
#pragma unroll
    for (int c = 0; c < HD; c++) qr[c] = q[(size_t)c * SQ + p];

    float m = -1e30f, l = 0.f;
    float acc[HD];
#pragma unroll
    for (int c = 0; c < HD; c++) acc[c] = 0.f;

    __shared__ float ks[HD][33];
    __shared__ float vs[HD][33];

    const float scale = 0.17677669529663687f;  // 1/sqrt(32)

    for (int k0 = 0; k0 < SK; k0 += 32) {
#pragma unroll
        for (int it = 0; it < 8; it++) {
            int i = threadIdx.x + it * 128;
            int c = i >> 5, kk = i & 31;
            ks[c][kk] = k[(size_t)c * SK + k0 + kk];
            vs[c][kk] = v[(size_t)c * SK + k0 + kk];
        }
        __syncthreads();

        float s[32];
        float mloc = m;
#pragma unroll
        for (int kk = 0; kk < 32; kk++) {
            float t = 0.f;
#pragma unroll
            for (int c = 0; c < HD; c++) t += qr[c] * ks[c][kk];
            t *= scale;
            s[kk] = t;
            mloc = fmaxf(mloc, t);
        }
        float corr = __expf(m - mloc);
        m = mloc;
        l *= corr;
#pragma unroll
        for (int c = 0; c < HD; c++) acc[c] *= corr;
#pragma unroll
        for (int kk = 0; kk < 32; kk++) {
            float pk = __expf(s[kk] - m);
            l += pk;
#pragma unroll
            for (int c = 0; c < HD; c++) acc[c] += pk * vs[c][kk];
        }
        __syncthreads();
    }

    const float inv = 1.f / l;

    // Stage through smem for (partially) coalesced store
    __shared__ float xs[128][HD + 1];
#pragma unroll
    for (int c = 0; c < HD; c++) xs[threadIdx.x][c] = acc[c] * inv;
    __syncthreads();

    float* __restrict__ xout = g_x + (size_t)n * SQ * INNER + h * HD;
#pragma unroll
    for (int it = 0; it < 32; it++) {
        int i = threadIdx.x + it * 128;
        int row = i >> 5, cc = i & 31;
        xout[(size_t)(p0 + row) * INNER + cc] = xs[row][cc];
    }
}

// ---------------------------------------------------------------------------
// Up-projection: out[p,n,d] = sum_e x[n,p,e] * Wup[d,e]
// Rows r = n*SQ + p (M = 16384), cols d (1024), K = 128.
// ---------------------------------------------------------------------------
__global__ void up_kernel(const float* __restrict__ Wup, float* __restrict__ out) {
    const int d0 = blockIdx.x * 64;
    const int r0 = blockIdx.y * 64;

    __shared__ float Xs[32][65];  // [e_off][r_off]
    __shared__ float Ws[32][65];  // [e_off][d_off]

    const int tid = threadIdx.x;
    const int tr = tid & 15;   // 4 rows each
    const int td = tid >> 4;   // 4 cols each

    float acc[4][4];
#pragma unroll
    for (int i = 0; i < 4; i++)
#pragma unroll
        for (int j = 0; j < 4; j++) acc[i][j] = 0.f;

    for (int e0 = 0; e0 < INNER; e0 += 32) {
#pragma unroll
        for (int it = 0; it < 8; it++) {
            int i = tid + it * 256;
            int ee = i & 31, rr = i >> 5;
            Xs[ee][rr] = g_x[(size_t)(r0 + rr) * INNER + e0 + ee];
            Ws[ee][rr] = Wup[(size_t)(d0 + rr) * INNER + e0 + ee];
        }
        __syncthreads();
#pragma unroll
        for (int kk = 0; kk < 32; kk++) {
            float a[4], b[4];
#pragma unroll
            for (int i = 0; i < 4; i++) a[i] = Xs[kk][tr * 4 + i];
#pragma unroll
            for (int j = 0; j < 4; j++) b[j] = Ws[kk][td * 4 + j];
#pragma unroll
            for (int i = 0; i < 4; i++)
#pragma unroll
                for (int j = 0; j < 4; j++) acc[i][j] += a[i] * b[j];
        }
        __syncthreads();
    }

#pragma unroll
    for (int i = 0; i < 4; i++) {
        int r = r0 + tr * 4 + i;
        int n = r >> 11;        // r / SQ
        int pp = r & 2047;      // r % SQ
#pragma unroll
        for (int j = 0; j < 4; j++) {
            out[((size_t)pp * NB + n) * DIM + d0 + td * 4 + j] = acc[i][j];
        }
    }
}

// ---------------------------------------------------------------------------
extern "C" void kernel_launch(void* const* d_in, const int* in_sizes, int n_in,
                              void* d_out, int out_size) {
    const float* query    = (const float*)d_in[0];
    const float* key_feat = (const float*)d_in[1];
    const float* Wq       = (const float*)d_in[2];
    const float* Wk       = (const float*)d_in[3];
    const float* Wv       = (const float*)d_in[4];
    const float* Wup      = (const float*)d_in[5];
    float* out            = (float*)d_out;

    dim3 g1(SK / 64, NB, 3);
    proj_kernel<<<g1, 256>>>(query, key_feat, Wq, Wk, Wv);

    dim3 g2(SQ / 128, NH, NB);
    attn_kernel<<<g2, 128>>>();

    dim3 g3(DIM / 64, (NB * SQ) / 64);
    up_kernel<<<g3, 256>>>(Wup, out);
}

// round 3
// speedup vs baseline: 1.1688x; 1.1682x over previous
#include <cuda_runtime.h>

#define SQ 2048
#define SK 2048
#define NB 8
#define DIM 1024
#define INNER 128
#define NH 4
#define HD 32

// Scratch (allocation-free): qkv projections + attention output
__device__ float g_qkv[3u * NB * INNER * SK];   // [sel][n][e][s]   25.2 MB
__device__ float g_x[(size_t)NB * SQ * INNER];  // [n][p][e]         8.4 MB

// ---------------------------------------------------------------------------
// Projection: C[e,s] = sum_d W[e,d] * X[s,n,d]   per (n, sel in {q,k,v})
// 128(e) x 128(s) block, BK=16, 256 threads, 8x8 microtile, LDS.128 reads.
// ---------------------------------------------------------------------------
__global__ __launch_bounds__(256, 2)
void proj_kernel(const float* __restrict__ query,
                 const float* __restrict__ key_feat,
                 const float* __restrict__ Wq,
                 const float* __restrict__ Wk,
                 const float* __restrict__ Wv) {
    const int s0  = blockIdx.x * 128;
    const int n   = blockIdx.y;
    const int sel = blockIdx.z;
    const float* __restrict__ X = (sel == 0) ? query : key_feat;
    const float* __restrict__ W = (sel == 0) ? Wq : (sel == 1 ? Wk : Wv);

    __shared__ float Ws[16][132];  // [d_off][e]  (132: float4-aligned pad)
    __shared__ float Xs[16][132];  // [d_off][s_off]

    const int tid = threadIdx.x;
    const int tx  = tid & 15;   // s dir, 8 each
    const int ty  = tid >> 4;   // e dir, 8 each

    float acc[8][8];
#pragma unroll
    for (int i = 0; i < 8; i++)
#pragma unroll
        for (int j = 0; j < 8; j++) acc[i][j] = 0.f;

    for (int d0 = 0; d0 < DIM; d0 += 16) {
        // A tile: 128 e x 16 d, transposed into smem
#pragma unroll
        for (int it = 0; it < 2; it++) {
            int f = tid + it * 256;
            int e = f >> 2, c4 = (f & 3) * 4;
            float4 w4 = *(const float4*)&W[(size_t)e * DIM + d0 + c4];
            Ws[c4 + 0][e] = w4.x; Ws[c4 + 1][e] = w4.y;
            Ws[c4 + 2][e] = w4.z; Ws[c4 + 3][e] = w4.w;
        }
        // B tile: 128 s x 16 d, transposed into smem
#pragma unroll
        for (int it = 0; it < 2; it++) {
            int f = tid + it * 256;
            int ss = f >> 2, c4 = (f & 3) * 4;
            float4 x4 = *(const float4*)&X[(size_t)(s0 + ss) * (NB * DIM) + (size_t)n * DIM + d0 + c4];
            Xs[c4 + 0][ss] = x4.x; Xs[c4 + 1][ss] = x4.y;
            Xs[c4 + 2][ss] = x4.z; Xs[c4 + 3][ss] = x4.w;
        }
        __syncthreads();

#pragma unroll
        for (int kk = 0; kk < 16; kk++) {
            float4 a0 = *(const float4*)&Ws[kk][ty * 8];
            float4 a1 = *(const float4*)&Ws[kk][ty * 8 + 4];
            float4 b0 = *(const float4*)&Xs[kk][tx * 8];
            float4 b1 = *(const float4*)&Xs[kk][tx * 8 + 4];
            float a[8] = {a0.x, a0.y, a0.z, a0.w, a1.x, a1.y, a1.z, a1.w};
            float b[8] = {b0.x, b0.y, b0.z, b0.w, b1.x, b1.y, b1.z, b1.w};
#pragma unroll
            for (int i = 0; i < 8; i++)
#pragma unroll
                for (int j = 0; j < 8; j++) acc[i][j] += a[i] * b[j];
        }
        __syncthreads();
    }

    float* __restrict__ out = g_qkv + ((size_t)sel * NB + n) * INNER * SK;
#pragma unroll
    for (int i = 0; i < 8; i++) {
        int e = ty * 8 + i;
        float* r = &out[(size_t)e * SK + s0 + tx * 8];
        *(float4*)r       = make_float4(acc[i][0], acc[i][1], acc[i][2], acc[i][3]);
        *(float4*)(r + 4) = make_float4(acc[i][4], acc[i][5], acc[i][6], acc[i][7]);
    }
}

// ---------------------------------------------------------------------------
// Flash attention: 1 thread = 1 query row, key-major smem tiles [kk][c],
// all inner-loop smem reads are broadcast LDS.128 (1 LDS per 4 FMA).
// ---------------------------------------------------------------------------
__global__ __launch_bounds__(128, 3)
void attn_kernel() {
    const int p0 = blockIdx.x * 128;
    const int p  = p0 + threadIdx.x;
    const int h  = blockIdx.y;
    const int n  = blockIdx.z;

    const float* __restrict__ q = g_qkv + ((size_t)0 * NB + n) * INNER * SK + (size_t)(h * HD) * SK;
    const float* __restrict__ k = g_qkv + ((size_t)1 * NB + n) * INNER * SK + (size_t)(h * HD) * SK;
    const float* __restrict__ v = g_qkv + ((size_t)2 * NB + n) * INNER * SK + (size_t)(h * HD) * SK;

    float qr[HD];
#pragma unroll
    for (int c = 0; c < HD; c++) qr[c] = q[(size_t)c * SQ + p];

    float m = -1e30f, l = 0.f;
    float acc[HD];
#pragma unroll
    for (int c = 0; c < HD; c++) acc[c] = 0.f;

    __shared__ float ks[32][36];   // [kk][c], pad 36 -> float4-aligned rows
    __shared__ float vs[32][36];

    const float scale = 0.17677669529663687f;  // 1/sqrt(32)

    for (int k0 = 0; k0 < SK; k0 += 32) {
        // load 32 keys x 32 dims (and values), gmem float4 coalesced
#pragma unroll
        for (int it = 0; it < 2; it++) {
            int f  = threadIdx.x + it * 128;
            int c  = f >> 3;           // 0..31 dim
            int k4 = (f & 7) * 4;      // key offset
            float4 kf = *(const float4*)&k[(size_t)c * SK + k0 + k4];
            ks[k4 + 0][c] = kf.x; ks[k4 + 1][c] = kf.y;
            ks[k4 + 2][c] = kf.z; ks[k4 + 3][c] = kf.w;
            float4 vf = *(const float4*)&v[(size_t)c * SK + k0 + k4];
            vs[k4 + 0][c] = vf.x; vs[k4 + 1][c] = vf.y;
            vs[k4 + 2][c] = vf.z; vs[k4 + 3][c] = vf.w;
        }
        __syncthreads();

        float s[32];
        float mloc = m;
#pragma unroll
        for (int kk = 0; kk < 32; kk++) {
            float t = 0.f;
#pragma unroll
            for (int c4 = 0; c4 < 32; c4 += 4) {
                float4 kv = *(const float4*)&ks[kk][c4];
                t += qr[c4 + 0] * kv.x + qr[c4 + 1] * kv.y
                   + qr[c4 + 2] * kv.z + qr[c4 + 3] * kv.w;
            }
            t *= scale;
            s[kk] = t;
            mloc = fmaxf(mloc, t);
        }
        float corr = __expf(m - mloc);
        m = mloc;
        l *= corr;
#pragma unroll
        for (int c = 0; c < HD; c++) acc[c] *= corr;
#pragma unroll
        for (int kk = 0; kk < 32; kk++) {
            float pk = __expf(s[kk] - m);
            l += pk;
#pragma unroll
            for (int c4 = 0; c4 < 32; c4 += 4) {
                float4 vv = *(const float4*)&vs[kk][c4];
                acc[c4 + 0] += pk * vv.x; acc[c4 + 1] += pk * vv.y;
                acc[c4 + 2] += pk * vv.z; acc[c4 + 3] += pk * vv.w;
            }
        }
        __syncthreads();
    }

    const float inv = 1.f / l;

    __shared__ float xs[128][HD + 1];
#pragma unroll
    for (int c = 0; c < HD; c++) xs[threadIdx.x][c] = acc[c] * inv;
    __syncthreads();

    float* __restrict__ xout = g_x + (size_t)n * SQ * INNER + h * HD;
#pragma unroll
    for (int it = 0; it < 32; it++) {
        int i = threadIdx.x + it * 128;
        int row = i >> 5, cc = i & 31;
        xout[(size_t)(p0 + row) * INNER + cc] = xs[row][cc];
    }
}

// ---------------------------------------------------------------------------
// Up-projection: out[p,n,d] = sum_e x[n,p,e] * Wup[d,e]
// GEMM M=16384(r) x N=1024(d) x K=128. Same 128x128 SGEMM template.
// ---------------------------------------------------------------------------
__global__ __launch_bounds__(256, 2)
void up_kernel(const float* __restrict__ Wup, float* __restrict__ out) {
    const int d0 = blockIdx.x * 128;
    const int r0 = blockIdx.y * 128;

    __shared__ float Xs[16][132];  // [e_off][r_off]
    __shared__ float Ws[16][132];  // [e_off][d_off]

    const int tid = threadIdx.x;
    const int tx  = tid & 15;   // d dir
    const int ty  = tid >> 4;   // r dir

    float acc[8][8];
#pragma unroll
    for (int i = 0; i < 8; i++)
#pragma unroll
        for (int j = 0; j < 8; j++) acc[i][j] = 0.f;

    for (int e0 = 0; e0 < INNER; e0 += 16) {
#pragma unroll
        for (int it = 0; it < 2; it++) {
            int f = tid + it * 256;
            int row = f >> 2, c4 = (f & 3) * 4;
            float4 x4 = *(const float4*)&g_x[(size_t)(r0 + row) * INNER + e0 + c4];
            Xs[c4 + 0][row] = x4.x; Xs[c4 + 1][row] = x4.y;
            Xs[c4 + 2][row] = x4.z; Xs[c4 + 3][row] = x4.w;
            float4 w4 = *(const float4*)&Wup[(size_t)(d0 + row) * INNER + e0 + c4];
            Ws[c4 + 0][row] = w4.x; Ws[c4 + 1][row] = w4.y;
            Ws[c4 + 2][row] = w4.z; Ws[c4 + 3][row] = w4.w;
        }
        __syncthreads();

#pragma unroll
        for (int kk = 0; kk < 16; kk++) {
            float4 a0 = *(const float4*)&Xs[kk][ty * 8];
            float4 a1 = *(const float4*)&Xs[kk][ty * 8 + 4];
            float4 b0 = *(const float4*)&Ws[kk][tx * 8];
            float4 b1 = *(const float4*)&Ws[kk][tx * 8 + 4];
            float a[8] = {a0.x, a0.y, a0.z, a0.w, a1.x, a1.y, a1.z, a1.w};
            float b[8] = {b0.x, b0.y, b0.z, b0.w, b1.x, b1.y, b1.z, b1.w};
#pragma unroll
            for (int i = 0; i < 8; i++)
#pragma unroll
                for (int j = 0; j < 8; j++) acc[i][j] += a[i] * b[j];
        }
        __syncthreads();
    }

#pragma unroll
    for (int i = 0; i < 8; i++) {
        int r = r0 + ty * 8 + i;
        int n  = r >> 11;       // r / SQ
        int pp = r & 2047;      // r % SQ
        float* o = &out[((size_t)pp * NB + n) * DIM + d0 + tx * 8];
        *(float4*)o       = make_float4(acc[i][0], acc[i][1], acc[i][2], acc[i][3]);
        *(float4*)(o + 4) = make_float4(acc[i][4], acc[i][5], acc[i][6], acc[i][7]);
    }
}

// ---------------------------------------------------------------------------
extern "C" void kernel_launch(void* const* d_in, const int* in_sizes, int n_in,
                              void* d_out, int out_size) {
    const float* query    = (const float*)d_in[0];
    const float* key_feat = (const float*)d_in[1];
    const float* Wq       = (const float*)d_in[2];
    const float* Wk       = (const float*)d_in[3];
    const float* Wv       = (const float*)d_in[4];
    const float* Wup      = (const float*)d_in[5];
    float* out            = (float*)d_out;

    dim3 g1(SK / 128, NB, 3);
    proj_kernel<<<g1, 256>>>(query, key_feat, Wq, Wk, Wv);

    dim3 g2(SQ / 128, NH, NB);
    attn_kernel<<<g2, 128>>>();

    dim3 g3(DIM / 128, (NB * SQ) / 128);
    up_kernel<<<g3, 256>>>(Wup, out);
}

// round 5
// speedup vs baseline: 1.4139x; 1.2097x over previous
#include <cuda_runtime.h>
#include <cuda_bf16.h>
#include <cstdint>

#define SQ 2048
#define SK 2048
#define NB 8
#define DIM 1024
#define INNER 128
#define NH 4
#define HD 32

// Scratch (allocation-free)
__device__ float g_qkv[3u * NB * INNER * SK];   // [sel][n][e][s]
__device__ float g_x[(size_t)NB * SQ * INNER];  // [n][p][e]

// ============================ warp-MMA helpers =============================
__device__ __forceinline__ uint32_t smem_u32(const void* p) {
    return (uint32_t)__cvta_generic_to_shared(p);
}
__device__ __forceinline__ void ldsm_x4(uint32_t& r0, uint32_t& r1,
                                        uint32_t& r2, uint32_t& r3, uint32_t addr) {
    asm volatile("ldmatrix.sync.aligned.m8n8.x4.shared.b16 {%0,%1,%2,%3}, [%4];"
                 : "=r"(r0), "=r"(r1), "=r"(r2), "=r"(r3) : "r"(addr));
}
__device__ __forceinline__ void mma_bf16(float* d, const uint32_t* a,
                                         uint32_t b0, uint32_t b1) {
    asm volatile(
        "mma.sync.aligned.m16n8k16.row.col.f32.bf16.bf16.f32 "
        "{%0,%1,%2,%3}, {%4,%5,%6,%7}, {%8,%9}, {%0,%1,%2,%3};"
        : "+f"(d[0]), "+f"(d[1]), "+f"(d[2]), "+f"(d[3])
        : "r"(a[0]), "r"(a[1]), "r"(a[2]), "r"(a[3]), "r"(b0), "r"(b1));
}

// Split one float into bf16 hi + bf16 lo (residual).
__device__ __forceinline__ void split2(float x, float y, uint32_t& hi, uint32_t& lo) {
    __nv_bfloat16 hx = __float2bfloat16(x);
    __nv_bfloat16 hy = __float2bfloat16(y);
    __nv_bfloat16 lx = __float2bfloat16(x - __bfloat162float(hx));
    __nv_bfloat16 ly = __float2bfloat16(y - __bfloat162float(hy));
    hi = (uint32_t)__bfloat16_as_ushort(hx) | ((uint32_t)__bfloat16_as_ushort(hy) << 16);
    lo = (uint32_t)__bfloat16_as_ushort(lx) | ((uint32_t)__bfloat16_as_ushort(ly) << 16);
}

// SMEM: 4 tiles (Ahi, Alo, Bhi, Blo), each 128 rows x 32 bf16, row stride 80B.
#define ROWB   80
#define TILE   (128 * ROWB)   // 10240
#define SM_AH  0
#define SM_AL  TILE
#define SM_BH  (2 * TILE)
#define SM_BL  (3 * TILE)

// Core: acc[4][4][4] (warp tile m64 x n32) += A(128xK) * B(128xK)^T,
// K = KCHUNKS*32, bf16 hi/lo 3-MMA split, register-prefetched K-chunks.
template <int KCHUNKS>
__device__ __forceinline__ void mma_gemm(const float* __restrict__ A, size_t lda,
                                         const float* __restrict__ B, size_t ldb,
                                         float acc[4][4][4], char* sm) {
    const int tid  = threadIdx.x;
    const int lane = tid & 31;
    const int wid  = tid >> 5;
    const int wm   = (wid >> 2) * 64;   // warp m offset
    const int wn   = (wid & 3) * 32;    // warp n offset
    const int seg  = tid & 7;           // 8 float4 segs per 32-col row
    const int rbase = tid >> 3;         // 32 rows per pass
    const uint32_t smb = smem_u32(sm);

    float4 va[4], vb[4];
#pragma unroll
    for (int p = 0; p < 4; p++) {
        va[p] = *(const float4*)(A + (size_t)(rbase + 32 * p) * lda + seg * 4);
        vb[p] = *(const float4*)(B + (size_t)(rbase + 32 * p) * ldb + seg * 4);
    }

    for (int c = 0; c < KCHUNKS; c++) {
        // convert + stage
#pragma unroll
        for (int p = 0; p < 4; p++) {
            int off = (rbase + 32 * p) * ROWB + seg * 8;
            uint2 h, l;
            split2(va[p].x, va[p].y, h.x, l.x);
            split2(va[p].z, va[p].w, h.y, l.y);
            *(uint2*)(sm + SM_AH + off) = h;
            *(uint2*)(sm + SM_AL + off) = l;
            split2(vb[p].x, vb[p].y, h.x, l.x);
            split2(vb[p].z, vb[p].w, h.y, l.y);
            *(uint2*)(sm + SM_BH + off) = h;
            *(uint2*)(sm + SM_BL + off) = l;
        }
        __syncthreads();

        if (c + 1 < KCHUNKS) {
            int co = (c + 1) * 32;
#pragma unroll
            for (int p = 0; p < 4; p++) {
                va[p] = *(const float4*)(A + (size_t)(rbase + 32 * p) * lda + co + seg * 4);
                vb[p] = *(const float4*)(B + (size_t)(rbase + 32 * p) * ldb + co + seg * 4);
            }
        }

#pragma unroll
        for (int ks = 0; ks < 2; ks++) {
            const int kb = ks * 32;  // byte offset: 16 bf16
            uint32_t ah[4][4], al[4][4];
#pragma unroll
            for (int im = 0; im < 4; im++) {
                uint32_t ra = smb + (wm + im * 16 + (lane & 15)) * ROWB + (lane >> 4) * 16 + kb;
                ldsm_x4(ah[im][0], ah[im][1], ah[im][2], ah[im][3], ra + SM_AH);
                ldsm_x4(al[im][0], al[im][1], al[im][2], al[im][3], ra + SM_AL);
            }
            uint32_t bh[2][4], bl[2][4];
#pragma unroll
            for (int i2 = 0; i2 < 2; i2++) {
                uint32_t rb = smb + (wn + i2 * 16 + (lane & 15)) * ROWB + (lane >> 4) * 16 + kb;
                ldsm_x4(bh[i2][0], bh[i2][1], bh[i2][2], bh[i2][3], rb + SM_BH);
                ldsm_x4(bl[i2][0], bl[i2][1], bl[i2][2], bl[i2][3], rb + SM_BL);
            }
#pragma unroll
            for (int im = 0; im < 4; im++) {
#pragma unroll
                for (int in = 0; in < 4; in++) {
                    int i2 = in >> 1, sub = in & 1;
                    uint32_t b0h = bh[i2][sub], b1h = bh[i2][sub + 2];
                    uint32_t b0l = bl[i2][sub], b1l = bl[i2][sub + 2];
                    mma_bf16(acc[im][in], ah[im], b0h, b1h);
                    mma_bf16(acc[im][in], ah[im], b0l, b1l);
                    mma_bf16(acc[im][in], al[im], b0h, b1h);
                }
            }
        }
        __syncthreads();
    }
}

// ---------------------------------------------------------------------------
// proj: C[e, s] = sum_d W[e,d] * X[s,n,d]  per (n, sel in {q,k,v})
// ---------------------------------------------------------------------------
__global__ __launch_bounds__(256, 1)
void proj_mma(const float* __restrict__ query, const float* __restrict__ key_feat,
              const float* __restrict__ Wq, const float* __restrict__ Wk,
              const float* __restrict__ Wv) {
    __shared__ __align__(16) char sm[4 * TILE];
    const int s0  = blockIdx.x * 128;
    const int n   = blockIdx.y;
    const int sel = blockIdx.z;
    const float* __restrict__ X = (sel == 0) ? query : key_feat;
    const float* __restrict__ W = (sel == 0) ? Wq : (sel == 1 ? Wk : Wv);

    float acc[4][4][4];
#pragma unroll
    for (int i = 0; i < 4; i++)
#pragma unroll
        for (int j = 0; j < 4; j++)
#pragma unroll
            for (int t = 0; t < 4; t++) acc[i][j][t] = 0.f;

    mma_gemm<32>(W, DIM, X + (size_t)s0 * (NB * DIM) + (size_t)n * DIM, (size_t)NB * DIM,
                 acc, sm);

    const int lane = threadIdx.x & 31, wid = threadIdx.x >> 5;
    const int wm = (wid >> 2) * 64, wn = (wid & 3) * 32;
    float* __restrict__ outp = g_qkv + ((size_t)sel * NB + n) * ((size_t)INNER * SK);
#pragma unroll
    for (int im = 0; im < 4; im++) {
#pragma unroll
        for (int in = 0; in < 4; in++) {
            int e = wm + im * 16 + (lane >> 2);
            int s = s0 + wn + in * 8 + (lane & 3) * 2;
            *(float2*)&outp[(size_t)e * SK + s]       = make_float2(acc[im][in][0], acc[im][in][1]);
            *(float2*)&outp[(size_t)(e + 8) * SK + s] = make_float2(acc[im][in][2], acc[im][in][3]);
        }
    }
}

// ---------------------------------------------------------------------------
// up: out[p,n,d] = sum_e x[r,e] * Wup[d,e],  r = n*SQ + p
// ---------------------------------------------------------------------------
__global__ __launch_bounds__(256, 1)
void up_mma(const float* __restrict__ Wup, float* __restrict__ out) {
    __shared__ __align__(16) char sm[4 * TILE];
    const int d0 = blockIdx.x * 128;
    const int r0 = blockIdx.y * 128;

    float acc[4][4][4];
#pragma unroll
    for (int i = 0; i < 4; i++)
#pragma unroll
        for (int j = 0; j < 4; j++)
#pragma unroll
            for (int t = 0; t < 4; t++) acc[i][j][t] = 0.f;

    mma_gemm<4>(g_x + (size_t)r0 * INNER, INNER, Wup + (size_t)d0 * INNER, INNER, acc, sm);

    const int lane = threadIdx.x & 31, wid = threadIdx.x >> 5;
    const int wm = (wid >> 2) * 64, wn = (wid & 3) * 32;
#pragma unroll
    for (int im = 0; im < 4; im++) {
#pragma unroll
        for (int in = 0; in < 4; in++) {
            int d = d0 + wn + in * 8 + (lane & 3) * 2;
#pragma unroll
            for (int half = 0; half < 2; half++) {
                int r = r0 + wm + im * 16 + (lane >> 2) + half * 8;
                int nn = r >> 11, pp = r & 2047;
                *(float2*)&out[((size_t)pp * NB + nn) * DIM + d] =
                    make_float2(acc[im][in][half * 2], acc[im][in][half * 2 + 1]);
            }
        }
    }
}

// ---------------------------------------------------------------------------
// Flash attention (SIMT): 1 thread = 1 query row.
// ---------------------------------------------------------------------------
__global__ __launch_bounds__(128, 3)
void attn_kernel() {
    const int p0 = blockIdx.x * 128;
    const int p  = p0 + threadIdx.x;
    const int h  = blockIdx.y;
    const int n  = blockIdx.z;

    const float* __restrict__ q = g_qkv + ((size_t)0 * NB + n) * INNER * SK + (size_t)(h * HD) * SK;
    const float* __restrict__ k = g_qkv + ((size_t)1 * NB + n) * INNER * SK + (size_t)(h * HD) * SK;
    const float* __restrict__ v = g_qkv + ((size_t)2 * NB + n) * INNER * SK + (size_t)(h * HD) * SK;

    float qr[HD];
#pragma unroll
    for (int c = 0; c < HD; c++) qr[c] = q[(size_t)c * SQ + p];

    float m = -1e30f, l = 0.f;
    float acc[HD];
#pragma unroll
    for (int c = 0; c < HD; c++) acc[c] = 0.f;

    __shared__ float ks[32][36];
    __shared__ float vs[32][36];

    const float scale = 0.17677669529663687f;

    for (int k0 = 0; k0 < SK; k0 += 32) {
#pragma unroll
        for (int it = 0; it < 2; it++) {
            int f  = threadIdx.x + it * 128;
            int c  = f >> 3;
            int k4 = (f & 7) * 4;
            float4 kf = *(const float4*)&k[(size_t)c * SK + k0 + k4];
            ks[k4 + 0][c] = kf.x; ks[k4 + 1][c] = kf.y;
            ks[k4 + 2][c] = kf.z; ks[k4 + 3][c] = kf.w;
            float4 vf = *(const float4*)&v[(size_t)c * SK + k0 + k4];
            vs[k4 + 0][c] = vf.x; vs[k4 + 1][c] = vf.y;
            vs[k4 + 2][c] = vf.z; vs[k4 + 3][c] = vf.w;
        }
        __syncthreads();

        float s[32];
        float mloc = m;
#pragma unroll
        for (int kk = 0; kk < 32; kk++) {
            float t = 0.f;
#pragma unroll
            for (int c4 = 0; c4 < 32; c4 += 4) {
                float4 kv = *(const float4*)&ks[kk][c4];
                t += qr[c4 + 0] * kv.x + qr[c4 + 1] * kv.y
                   + qr[c4 + 2] * kv.z + qr[c4 + 3] * kv.w;
            }
            t *= scale;
            s[kk] = t;
            mloc = fmaxf(mloc, t);
        }
        float corr = __expf(m - mloc);
        m = mloc;
        l *= corr;
#pragma unroll
        for (int c = 0; c < HD; c++) acc[c] *= corr;
#pragma unroll
        for (int kk = 0; kk < 32; kk++) {
            float pk = __expf(s[kk] - m);
            l += pk;
#pragma unroll
            for (int c4 = 0; c4 < 32; c4 += 4) {
                float4 vv = *(const float4*)&vs[kk][c4];
                acc[c4 + 0] += pk * vv.x; acc[c4 + 1] += pk * vv.y;
                acc[c4 + 2] += pk * vv.z; acc[c4 + 3] += pk * vv.w;
            }
        }
        __syncthreads();
    }

    const float inv = 1.f / l;

    __shared__ float xs[128][HD + 1];
#pragma unroll
    for (int c = 0; c < HD; c++) xs[threadIdx.x][c] = acc[c] * inv;
    __syncthreads();

    float* __restrict__ xout = g_x + (size_t)n * SQ * INNER + h * HD;
#pragma unroll
    for (int it = 0; it < 32; it++) {
        int i = threadIdx.x + it * 128;
        int row = i >> 5, cc = i & 31;
        xout[(size_t)(p0 + row) * INNER + cc] = xs[row][cc];
    }
}

// ---------------------------------------------------------------------------
extern "C" void kernel_launch(void* const* d_in, const int* in_sizes, int n_in,
                              void* d_out, int out_size) {
    const float* query    = (const float*)d_in[0];
    const float* key_feat = (const float*)d_in[1];
    const float* Wq       = (const float*)d_in[2];
    const float* Wk       = (const float*)d_in[3];
    const float* Wv       = (const float*)d_in[4];
    const float* Wup      = (const float*)d_in[5];
    float* out            = (float*)d_out;

    dim3 g1(SK / 128, NB, 3);
    proj_mma<<<g1, 256>>>(query, key_feat, Wq, Wk, Wv);

    dim3 g2(SQ / 128, NH, NB);
    attn_kernel<<<g2, 128>>>();

    dim3 g3(DIM / 128, (NB * SQ) / 128);
    up_mma<<<g3, 256>>>(Wup, out);
}

// round 6
// speedup vs baseline: 3.1723x; 2.2436x over previous
#include <cuda_runtime.h>
#include <cuda_bf16.h>
#include <cstdint>

#define SQ 2048
#define SK 2048
#define NB 8
#define DIM 1024
#define INNER 128
#define NH 4
#define HD 32

// Scratch (allocation-free)
__device__ float g_qkv[3u * NB * INNER * SK];   // [sel][n][e][s]
__device__ float g_x[(size_t)NB * SQ * INNER];  // [n][p][e]

// ============================ warp-MMA helpers =============================
__device__ __forceinline__ uint32_t smem_u32(const void* p) {
    return (uint32_t)__cvta_generic_to_shared(p);
}
__device__ __forceinline__ void ldsm_x4(uint32_t& r0, uint32_t& r1,
                                        uint32_t& r2, uint32_t& r3, uint32_t addr) {
    asm volatile("ldmatrix.sync.aligned.m8n8.x4.shared.b16 {%0,%1,%2,%3}, [%4];"
                 : "=r"(r0), "=r"(r1), "=r"(r2), "=r"(r3) : "r"(addr));
}
__device__ __forceinline__ void mma_bf16(float* d, const uint32_t* a,
                                         uint32_t b0, uint32_t b1) {
    asm volatile(
        "mma.sync.aligned.m16n8k16.row.col.f32.bf16.bf16.f32 "
        "{%0,%1,%2,%3}, {%4,%5,%6,%7}, {%8,%9}, {%0,%1,%2,%3};"
        : "+f"(d[0]), "+f"(d[1]), "+f"(d[2]), "+f"(d[3])
        : "r"(a[0]), "r"(a[1]), "r"(a[2]), "r"(a[3]), "r"(b0), "r"(b1));
}
__device__ __forceinline__ float ex2f(float x) {
    float y;
    asm("ex2.approx.f32 %0, %1;" : "=f"(y) : "f"(x));
    return y;
}

// Split (x, y) into packed bf16 hi pair + bf16 residual-lo pair.
__device__ __forceinline__ void split2(float x, float y, uint32_t& hi, uint32_t& lo) {
    __nv_bfloat16 hx = __float2bfloat16(x);
    __nv_bfloat16 hy = __float2bfloat16(y);
    __nv_bfloat16 lx = __float2bfloat16(x - __bfloat162float(hx));
    __nv_bfloat16 ly = __float2bfloat16(y - __bfloat162float(hy));
    hi = (uint32_t)__bfloat16_as_ushort(hx) | ((uint32_t)__bfloat16_as_ushort(hy) << 16);
    lo = (uint32_t)__bfloat16_as_ushort(lx) | ((uint32_t)__bfloat16_as_ushort(ly) << 16);
}

// ===================== GEMM template (proj / up, unchanged R4) =============
#define ROWB   80
#define TILE   (128 * ROWB)
#define SM_AH  0
#define SM_AL  TILE
#define SM_BH  (2 * TILE)
#define SM_BL  (3 * TILE)

template <int KCHUNKS>
__device__ __forceinline__ void mma_gemm(const float* __restrict__ A, size_t lda,
                                         const float* __restrict__ B, size_t ldb,
                                         float acc[4][4][4], char* sm) {
    const int tid  = threadIdx.x;
    const int lane = tid & 31;
    const int wid  = tid >> 5;
    const int wm   = (wid >> 2) * 64;
    const int wn   = (wid & 3) * 32;
    const int seg  = tid & 7;
    const int rbase = tid >> 3;
    const uint32_t smb = smem_u32(sm);

    float4 va[4], vb[4];
#pragma unroll
    for (int p = 0; p < 4; p++) {
        va[p] = *(const float4*)(A + (size_t)(rbase + 32 * p) * lda + seg * 4);
        vb[p] = *(const float4*)(B + (size_t)(rbase + 32 * p) * ldb + seg * 4);
    }

    for (int c = 0; c < KCHUNKS; c++) {
#pragma unroll
        for (int p = 0; p < 4; p++) {
            int off = (rbase + 32 * p) * ROWB + seg * 8;
            uint2 h, l;
            split2(va[p].x, va[p].y, h.x, l.x);
            split2(va[p].z, va[p].w, h.y, l.y);
            *(uint2*)(sm + SM_AH + off) = h;
            *(uint2*)(sm + SM_AL + off) = l;
            split2(vb[p].x, vb[p].y, h.x, l.x);
            split2(vb[p].z, vb[p].w, h.y, l.y);
            *(uint2*)(sm + SM_BH + off) = h;
            *(uint2*)(sm + SM_BL + off) = l;
        }
        __syncthreads();

        if (c + 1 < KCHUNKS) {
            int co = (c + 1) * 32;
#pragma unroll
            for (int p = 0; p < 4; p++) {
                va[p] = *(const float4*)(A + (size_t)(rbase + 32 * p) * lda + co + seg * 4);
                vb[p] = *(const float4*)(B + (size_t)(rbase + 32 * p) * ldb + co + seg * 4);
            }
        }

#pragma unroll
        for (int ks = 0; ks < 2; ks++) {
            const int kb = ks * 32;
            uint32_t ah[4][4], al[4][4];
#pragma unroll
            for (int im = 0; im < 4; im++) {
                uint32_t ra = smb + (wm + im * 16 + (lane & 15)) * ROWB + (lane >> 4) * 16 + kb;
                ldsm_x4(ah[im][0], ah[im][1], ah[im][2], ah[im][3], ra + SM_AH);
                ldsm_x4(al[im][0], al[im][1], al[im][2], al[im][3], ra + SM_AL);
            }
            uint32_t bh[2][4], bl[2][4];
#pragma unroll
            for (int i2 = 0; i2 < 2; i2++) {
                uint32_t rb = smb + (wn + i2 * 16 + (lane & 15)) * ROWB + (lane >> 4) * 16 + kb;
                ldsm_x4(bh[i2][0], bh[i2][1], bh[i2][2], bh[i2][3], rb + SM_BH);
                ldsm_x4(bl[i2][0], bl[i2][1], bl[i2][2], bl[i2][3], rb + SM_BL);
            }
#pragma unroll
            for (int im = 0; im < 4; im++) {
#pragma unroll
                for (int in = 0; in < 4; in++) {
                    int i2 = in >> 1, sub = in & 1;
                    mma_bf16(acc[im][in], ah[im], bh[i2][sub], bh[i2][sub + 2]);
                    mma_bf16(acc[im][in], ah[im], bl[i2][sub], bl[i2][sub + 2]);
                    mma_bf16(acc[im][in], al[im], bh[i2][sub], bh[i2][sub + 2]);
                }
            }
        }
        __syncthreads();
    }
}

__global__ __launch_bounds__(256, 1)
void proj_mma(const float* __restrict__ query, const float* __restrict__ key_feat,
              const float* __restrict__ Wq, const float* __restrict__ Wk,
              const float* __restrict__ Wv) {
    __shared__ __align__(16) char sm[4 * TILE];
    const int s0  = blockIdx.x * 128;
    const int n   = blockIdx.y;
    const int sel = blockIdx.z;
    const float* __restrict__ X = (sel == 0) ? query : key_feat;
    const float* __restrict__ W = (sel == 0) ? Wq : (sel == 1 ? Wk : Wv);

    float acc[4][4][4];
#pragma unroll
    for (int i = 0; i < 4; i++)
#pragma unroll
        for (int j = 0; j < 4; j++)
#pragma unroll
            for (int t = 0; t < 4; t++) acc[i][j][t] = 0.f;

    mma_gemm<32>(W, DIM, X + (size_t)s0 * (NB * DIM) + (size_t)n * DIM, (size_t)NB * DIM,
                 acc, sm);

    const int lane = threadIdx.x & 31, wid = threadIdx.x >> 5;
    const int wm = (wid >> 2) * 64, wn = (wid & 3) * 32;
    float* __restrict__ outp = g_qkv + ((size_t)sel * NB + n) * ((size_t)INNER * SK);
#pragma unroll
    for (int im = 0; im < 4; im++) {
#pragma unroll
        for (int in = 0; in < 4; in++) {
            int e = wm + im * 16 + (lane >> 2);
            int s = s0 + wn + in * 8 + (lane & 3) * 2;
            *(float2*)&outp[(size_t)e * SK + s]       = make_float2(acc[im][in][0], acc[im][in][1]);
            *(float2*)&outp[(size_t)(e + 8) * SK + s] = make_float2(acc[im][in][2], acc[im][in][3]);
        }
    }
}

__global__ __launch_bounds__(256, 1)
void up_mma(const float* __restrict__ Wup, float* __restrict__ out) {
    __shared__ __align__(16) char sm[4 * TILE];
    const int d0 = blockIdx.x * 128;
    const int r0 = blockIdx.y * 128;

    float acc[4][4][4];
#pragma unroll
    for (int i = 0; i < 4; i++)
#pragma unroll
        for (int j = 0; j < 4; j++)
#pragma unroll
            for (int t = 0; t < 4; t++) acc[i][j][t] = 0.f;

    mma_gemm<4>(g_x + (size_t)r0 * INNER, INNER, Wup + (size_t)d0 * INNER, INNER, acc, sm);

    const int lane = threadIdx.x & 31, wid = threadIdx.x >> 5;
    const int wm = (wid >> 2) * 64, wn = (wid & 3) * 32;
#pragma unroll
    for (int im = 0; im < 4; im++) {
#pragma unroll
        for (int in = 0; in < 4; in++) {
            int d = d0 + wn + in * 8 + (lane & 3) * 2;
#pragma unroll
            for (int half = 0; half < 2; half++) {
                int r = r0 + wm + im * 16 + (lane >> 2) + half * 8;
                int nn = r >> 11, pp = r & 2047;
                *(float2*)&out[((size_t)pp * NB + nn) * DIM + d] =
                    make_float2(acc[im][in][half * 2], acc[im][in][half * 2 + 1]);
            }
        }
    }
}

// ===================== Flash attention on HMMA =============================
// CTA: 128 queries x (n,h). 4 warps x 32 queries. KV chunk = 64 keys.
// smem strides chosen so fragment LDS hits all 32 banks (no conflicts).
#define QP 136   // uint32 pitch for Q staging  [16 cpairs][128 queries]
#define KP 72    // uint32 pitch for K staging  [16 cpairs][64 keys]
#define VP 36    // uint32 pitch for V staging  [32 ch][32 keypairs]

__global__ __launch_bounds__(128, 2)
void attn_mma() {
    const int p0 = blockIdx.x * 128;
    const int h  = blockIdx.y;
    const int n  = blockIdx.z;

    const float* __restrict__ q = g_qkv + ((size_t)0 * NB + n) * ((size_t)INNER * SK) + (size_t)(h * HD) * SK;
    const float* __restrict__ k = g_qkv + ((size_t)1 * NB + n) * ((size_t)INNER * SK) + (size_t)(h * HD) * SK;
    const float* __restrict__ v = g_qkv + ((size_t)2 * NB + n) * ((size_t)INNER * SK) + (size_t)(h * HD) * SK;

    __shared__ uint32_t qsh[16 * QP], qsl[16 * QP];
    __shared__ uint32_t ksh[16 * KP], ksl[16 * KP];
    __shared__ uint32_t vsh[32 * VP], vsl[32 * VP];

    const int tid  = threadIdx.x;
    const int lane = tid & 31;
    const int w    = tid >> 5;

    // ---- stage Q (once): [cpair][query] packed bf16 pairs, hi/lo ----
#pragma unroll
    for (int t4 = 0; t4 < 4; t4++) {
        int task = tid + t4 * 128;        // 0..511
        int cp = task >> 5, qg = task & 31;
        int qq = qg * 4;
        float4 f0 = *(const float4*)&q[(size_t)(2 * cp) * SK + p0 + qq];
        float4 f1 = *(const float4*)&q[(size_t)(2 * cp + 1) * SK + p0 + qq];
        uint4 hh, ll;
        split2(f0.x, f1.x, hh.x, ll.x);
        split2(f0.y, f1.y, hh.y, ll.y);
        split2(f0.z, f1.z, hh.z, ll.z);
        split2(f0.w, f1.w, hh.w, ll.w);
        *(uint4*)&qsh[cp * QP + qq] = hh;
        *(uint4*)&qsl[cp * QP + qq] = ll;
    }
    __syncthreads();

    // ---- load Q fragments into registers (reused for all 32 chunks) ----
    uint32_t qfh[2][2][4], qfl[2][2][4];   // [mtile][kstep][reg]
#pragma unroll
    for (int im = 0; im < 2; im++) {
#pragma unroll
        for (int ks = 0; ks < 2; ks++) {
            int row = w * 32 + im * 16 + (lane >> 2);
            int cp  = (lane & 3) + ks * 8;
            qfh[im][ks][0] = qsh[cp * QP + row];
            qfh[im][ks][1] = qsh[cp * QP + row + 8];
            qfh[im][ks][2] = qsh[(cp + 4) * QP + row];
            qfh[im][ks][3] = qsh[(cp + 4) * QP + row + 8];
            qfl[im][ks][0] = qsl[cp * QP + row];
            qfl[im][ks][1] = qsl[cp * QP + row + 8];
            qfl[im][ks][2] = qsl[(cp + 4) * QP + row];
            qfl[im][ks][3] = qsl[(cp + 4) * QP + row + 8];
        }
    }

    float oacc[2][4][4];
#pragma unroll
    for (int im = 0; im < 2; im++)
#pragma unroll
        for (int nt = 0; nt < 4; nt++)
#pragma unroll
            for (int t = 0; t < 4; t++) oacc[im][nt][t] = 0.f;
    float rowm[2][2] = {{-1e30f, -1e30f}, {-1e30f, -1e30f}};
    float rowl[2][2] = {{0.f, 0.f}, {0.f, 0.f}};

    const float SC2 = 0.17677669529663687f * 1.4426950408889634f;  // scale*log2(e)

    for (int k0 = 0; k0 < SK; k0 += 64) {
        // ---- stage K chunk: [cpair][key], hi/lo ----
#pragma unroll
        for (int t2 = 0; t2 < 2; t2++) {
            int task = tid + t2 * 128;     // 0..255
            int cp = task >> 4, kg = task & 15;
            int kk = kg * 4;
            float4 f0 = *(const float4*)&k[(size_t)(2 * cp) * SK + k0 + kk];
            float4 f1 = *(const float4*)&k[(size_t)(2 * cp + 1) * SK + k0 + kk];
            uint4 hh, ll;
            split2(f0.x, f1.x, hh.x, ll.x);
            split2(f0.y, f1.y, hh.y, ll.y);
            split2(f0.z, f1.z, hh.z, ll.z);
            split2(f0.w, f1.w, hh.w, ll.w);
            *(uint4*)&ksh[cp * KP + kk] = hh;
            *(uint4*)&ksl[cp * KP + kk] = ll;
        }
        // ---- stage V chunk: [ch][keypair], hi/lo ----
#pragma unroll
        for (int t4 = 0; t4 < 4; t4++) {
            int task = tid + t4 * 128;     // 0..511
            int c = task >> 4, kg = task & 15;
            int kk = kg * 4;
            float4 f = *(const float4*)&v[(size_t)c * SK + k0 + kk];
            uint2 hh, ll;
            split2(f.x, f.y, hh.x, ll.x);
            split2(f.z, f.w, hh.y, ll.y);
            *(uint2*)&vsh[c * VP + (kk >> 1)] = hh;
            *(uint2*)&vsl[c * VP + (kk >> 1)] = ll;
        }
        __syncthreads();

        // ---- S = Q K^T (warp: 32q x 64k), 3-MMA hi/lo split ----
        float sacc[2][8][4];
#pragma unroll
        for (int im = 0; im < 2; im++)
#pragma unroll
            for (int in = 0; in < 8; in++)
#pragma unroll
                for (int t = 0; t < 4; t++) sacc[im][in][t] = 0.f;

#pragma unroll
        for (int ks = 0; ks < 2; ks++) {
            uint32_t bh[8][2], bl[8][2];
#pragma unroll
            for (int in = 0; in < 8; in++) {
                int cp = (lane & 3) + ks * 8;
                int ky = in * 8 + (lane >> 2);
                bh[in][0] = ksh[cp * KP + ky];
                bh[in][1] = ksh[(cp + 4) * KP + ky];
                bl[in][0] = ksl[cp * KP + ky];
                bl[in][1] = ksl[(cp + 4) * KP + ky];
            }
#pragma unroll
            for (int im = 0; im < 2; im++)
#pragma unroll
                for (int in = 0; in < 8; in++) {
                    mma_bf16(sacc[im][in], qfh[im][ks], bh[in][0], bh[in][1]);
                    mma_bf16(sacc[im][in], qfh[im][ks], bl[in][0], bl[in][1]);
                    mma_bf16(sacc[im][in], qfl[im][ks], bh[in][0], bh[in][1]);
                }
        }

        // ---- online softmax on register fragments ----
#pragma unroll
        for (int im = 0; im < 2; im++) {
#pragma unroll
            for (int rs = 0; rs < 2; rs++) {
                float mx = rowm[im][rs];
#pragma unroll
                for (int in = 0; in < 8; in++)
                    mx = fmaxf(mx, fmaxf(sacc[im][in][rs * 2], sacc[im][in][rs * 2 + 1]));
                mx = fmaxf(mx, __shfl_xor_sync(0xffffffffu, mx, 1));
                mx = fmaxf(mx, __shfl_xor_sync(0xffffffffu, mx, 2));
                float corr = ex2f((rowm[im][rs] - mx) * SC2);
                rowm[im][rs] = mx;
                float sum = 0.f;
#pragma unroll
                for (int in = 0; in < 8; in++) {
                    float e0 = ex2f((sacc[im][in][rs * 2] - mx) * SC2);
                    float e1 = ex2f((sacc[im][in][rs * 2 + 1] - mx) * SC2);
                    sacc[im][in][rs * 2] = e0;
                    sacc[im][in][rs * 2 + 1] = e1;
                    sum += e0 + e1;
                }
                rowl[im][rs] = rowl[im][rs] * corr + sum;
#pragma unroll
                for (int nt = 0; nt < 4; nt++) {
                    oacc[im][nt][rs * 2] *= corr;
                    oacc[im][nt][rs * 2 + 1] *= corr;
                }
            }
        }

        // ---- O += P V^T: C-fragment -> A-fragment reuse + hi/lo split ----
#pragma unroll
        for (int ks4 = 0; ks4 < 4; ks4++) {
            uint32_t pfh[2][4], pfl[2][4];
#pragma unroll
            for (int im = 0; im < 2; im++) {
                const float* t0 = sacc[im][2 * ks4];
                const float* t1 = sacc[im][2 * ks4 + 1];
                split2(t0[0], t0[1], pfh[im][0], pfl[im][0]);
                split2(t0[2], t0[3], pfh[im][1], pfl[im][1]);
                split2(t1[0], t1[1], pfh[im][2], pfl[im][2]);
                split2(t1[2], t1[3], pfh[im][3], pfl[im][3]);
            }
            uint32_t bh[4][2], bl[4][2];
#pragma unroll
            for (int nt = 0; nt < 4; nt++) {
                int c  = nt * 8 + (lane >> 2);
                int kp = (lane & 3) + ks4 * 8;
                bh[nt][0] = vsh[c * VP + kp];
                bh[nt][1] = vsh[c * VP + kp + 4];
                bl[nt][0] = vsl[c * VP + kp];
                bl[nt][1] = vsl[c * VP + kp + 4];
            }
#pragma unroll
            for (int im = 0; im < 2; im++)
#pragma unroll
                for (int nt = 0; nt < 4; nt++) {
                    mma_bf16(oacc[im][nt], pfh[im], bh[nt][0], bh[nt][1]);
                    mma_bf16(oacc[im][nt], pfl[im], bh[nt][0], bh[nt][1]);
                    mma_bf16(oacc[im][nt], pfh[im], bl[nt][0], bl[nt][1]);
                }
        }
        __syncthreads();
    }

    // ---- finalize: 1/l and store to g_x [n][p][h*32 + c] ----
#pragma unroll
    for (int im = 0; im < 2; im++) {
#pragma unroll
        for (int rs = 0; rs < 2; rs++) {
            float l = rowl[im][rs];
            l += __shfl_xor_sync(0xffffffffu, l, 1);
            l += __shfl_xor_sync(0xffffffffu, l, 2);
            float inv = 1.f / l;
#pragma unroll
            for (int nt = 0; nt < 4; nt++) {
                oacc[im][nt][rs * 2] *= inv;
                oacc[im][nt][rs * 2 + 1] *= inv;
            }
        }
    }
    float* __restrict__ xout = g_x + (size_t)n * SQ * INNER + h * HD;
#pragma unroll
    for (int im = 0; im < 2; im++) {
#pragma unroll
        for (int nt = 0; nt < 4; nt++) {
            int row = p0 + w * 32 + im * 16 + (lane >> 2);
            int col = nt * 8 + (lane & 3) * 2;
            *(float2*)&xout[(size_t)row * INNER + col] =
                make_float2(oacc[im][nt][0], oacc[im][nt][1]);
            *(float2*)&xout[(size_t)(row + 8) * INNER + col] =
                make_float2(oacc[im][nt][2], oacc[im][nt][3]);
        }
    }
}

// ---------------------------------------------------------------------------
extern "C" void kernel_launch(void* const* d_in, const int* in_sizes, int n_in,
                              void* d_out, int out_size) {
    const float* query    = (const float*)d_in[0];
    const float* key_feat = (const float*)d_in[1];
    const float* Wq       = (const float*)d_in[2];
    const float* Wk       = (const float*)d_in[3];
    const float* Wv       = (const float*)d_in[4];
    const float* Wup      = (const float*)d_in[5];
    float* out            = (float*)d_out;

    dim3 g1(SK / 128, NB, 3);
    proj_mma<<<g1, 256>>>(query, key_feat, Wq, Wk, Wv);

    dim3 g2(SQ / 128, NH, NB);
    attn_mma<<<g2, 128>>>();

    dim3 g3(DIM / 128, (NB * SQ) / 128);
    up_mma<<<g3, 256>>>(Wup, out);
}